// round 2
// baseline (speedup 1.0000x reference)
#include <cuda_runtime.h>
#include <cuda_bf16.h>
#include <cstdint>

// Problem constants
#define BB 8
#define CHN 512
#define HH 80
#define WW 80
#define HW 6400
#define CR 32

// ---------------- device scratch ----------------
__device__ float g_means[2 * BB * CHN * 160];   // [z][b][c][160] : 0..79 h-mean, 80..159 w-mean
__device__ float g_yz[2 * BB * CR * 160];       // [z][b][cr][160]
__device__ float g_s[4 * BB * CHN * 80];        // [a][b][o][80] : a = {sh1, sw1, sh2, sw2}

// ---------------- helpers ----------------
__device__ __forceinline__ unsigned f2tf32(float x) {
    unsigned u;
    asm("cvt.rna.tf32.f32 %0, %1;" : "=r"(u) : "f"(x));
    return u;
}

__device__ __forceinline__ void mma_tf32(float d[4], const unsigned a[4], const unsigned b[2]) {
    asm volatile(
        "mma.sync.aligned.m16n8k8.row.col.f32.tf32.tf32.f32 "
        "{%0,%1,%2,%3}, {%4,%5,%6,%7}, {%8,%9}, {%0,%1,%2,%3};\n"
        : "+f"(d[0]), "+f"(d[1]), "+f"(d[2]), "+f"(d[3])
        : "r"(a[0]), "r"(a[1]), "r"(a[2]), "r"(a[3]), "r"(b[0]), "r"(b[1]));
}

// ---------------- kernel A: H-means and W-means of rgb and t ----------------
__global__ void mean_kernel(const float* __restrict__ rgb, const float* __restrict__ t) {
    const int c = blockIdx.x;
    const int b = blockIdx.y;
    const int z = blockIdx.z;
    const float* src = (z ? t : rgb) + ((size_t)(b * CHN) + c) * HW;
    __shared__ float sm[HW];
    const int tid = threadIdx.x;
    for (int i = tid; i < HW; i += 256) sm[i] = src[i];
    __syncthreads();
    float* dst = g_means + (((size_t)z * BB + b) * CHN + c) * 160;
    if (tid < 80) {
        // mean over w for row h = tid
        float s = 0.f;
        #pragma unroll 8
        for (int w = 0; w < 80; ++w) s += sm[tid * 80 + w];
        dst[tid] = s * (1.f / 80.f);
    } else if (tid < 160) {
        // mean over h for col w = tid-80
        const int w = tid - 80;
        float s = 0.f;
        #pragma unroll 8
        for (int h = 0; h < 80; ++h) s += sm[h * 80 + w];
        dst[tid] = s * (1.f / 80.f);
    }
}

// ---------------- kernel B1: y = BN(relu path) of w_r1 @ means_rgb ; z = relu(w_t1 @ means_t) ----------------
__global__ void yz_kernel(const float* __restrict__ w_r1, const float* __restrict__ w_t1,
                          const float* __restrict__ bn_g, const float* __restrict__ bn_b,
                          const float* __restrict__ bn_m, const float* __restrict__ bn_v) {
    const int p = blockIdx.x;    // 0..159
    const int b = blockIdx.y;    // 0..7
    const int z = blockIdx.z;    // 0: rgb path (BN), 1: t path
    const float* wsrc = z ? w_t1 : w_r1;                       // (32, 512)
    const float* x = g_means + (((size_t)z * BB + b) * CHN) * 160 + p;  // x[c] at [c*160]
    const int tid = threadIdx.x;
    const int cr = tid & 31;
    const int kg = tid >> 5;     // 8 k-groups of 64
    float partial = 0.f;
    const int c0 = kg * 64;
    #pragma unroll 8
    for (int c = c0; c < c0 + 64; ++c)
        partial += wsrc[cr * CHN + c] * x[(size_t)c * 160];
    __shared__ float red[8][32];
    red[kg][cr] = partial;
    __syncthreads();
    if (tid < 32) {
        float s = 0.f;
        #pragma unroll
        for (int g = 0; g < 8; ++g) s += red[g][tid];
        if (z == 0) {
            const float sc = bn_g[tid] * rsqrtf(bn_v[tid] + 1e-5f);
            s = s * sc + (bn_b[tid] - bn_m[tid] * sc);
        }
        s = fmaxf(s, 0.f);
        g_yz[(((size_t)z * BB + b) * CR + tid) * 160 + p] = s;
    }
}

// ---------------- kernel B2: sigmoid gates s_h1, s_w1, s_h2, s_w2 ----------------
__global__ void s_kernel(const float* __restrict__ w_fh1, const float* __restrict__ w_fw1,
                         const float* __restrict__ w_fh2, const float* __restrict__ w_fw2) {
    const int a = blockIdx.x;    // 0..3
    const int b = blockIdx.y;    // 0..7
    const float* wp = (a == 0) ? w_fh1 : (a == 1) ? w_fw1 : (a == 2) ? w_fh2 : w_fw2;  // (512, 32)
    const int z = a >> 1;        // 0: y, 1: z
    const int off = (a & 1) * 80;
    __shared__ float ys[CR][80];
    const int tid = threadIdx.x;
    for (int i = tid; i < CR * 80; i += 256) {
        const int cr = i / 80, p = i % 80;
        ys[cr][p] = g_yz[(((size_t)z * BB + b) * CR + cr) * 160 + off + p];
    }
    __syncthreads();
    for (int idx = tid; idx < CHN * 80; idx += 256) {
        const int o = idx / 80, h = idx % 80;
        float s = 0.f;
        #pragma unroll
        for (int cr = 0; cr < CR; ++cr) s += wp[o * CR + cr] * ys[cr][h];
        s = 1.f / (1.f + __expf(-s));
        g_s[(((size_t)a * BB + b) * CHN + o) * 80 + h] = s;
    }
}

// ---------------- kernel C: main tf32 GEMM + gated epilogue ----------------
// Per batch b: C[o,p] = sum_k W[o,k] * X[b,k,p];  X = [rgb ; t] along k.
// out[o,p] = C[o,p] * (sh1[o,h]*sw1[o,w] + sh2[o,h]*sw2[o,w]), p = h*80 + w.
#define BM 128
#define BN 128
#define BK 32
#define AS_STRIDE 36    // banks: 4q + j -> conflict-free
#define XS_STRIDE 136   // banks: 8j + q -> conflict-free

__global__ __launch_bounds__(256, 2)
void gemm_kernel(const float* __restrict__ rgb, const float* __restrict__ t,
                 const float* __restrict__ w_fuse, float* __restrict__ out) {
    __shared__ unsigned As[BM * AS_STRIDE];
    __shared__ unsigned Xs[BK * XS_STRIDE];

    const int b  = blockIdx.z;
    const int o0 = blockIdx.y * BM;
    const int p0 = blockIdx.x * BN;
    const int tid  = threadIdx.x;
    const int lane = tid & 31;
    const int warp = tid >> 5;
    const int wm = warp >> 2;      // 0..1  (64 rows each)
    const int wn = warp & 3;       // 0..3  (32 cols each)

    const float* rgbB = rgb + (size_t)b * CHN * HW;
    const float* tB   = t   + (size_t)b * CHN * HW;

    float acc[4][4][4];
    #pragma unroll
    for (int i = 0; i < 4; ++i)
        #pragma unroll
        for (int j = 0; j < 4; ++j)
            #pragma unroll
            for (int e = 0; e < 4; ++e) acc[i][j][e] = 0.f;

    for (int kt = 0; kt < 1024 / BK; ++kt) {
        const int k0 = kt * BK;
        const float* xb = (k0 < CHN) ? rgbB : tB;
        const int krow = k0 & (CHN - 1);
        if (kt) __syncthreads();
        // A tile: W[o0..o0+127][k0..k0+31]
        #pragma unroll
        for (int ps = 0; ps < 4; ++ps) {
            const int row = (tid >> 3) + ps * 32;
            const int kq  = (tid & 7) * 4;
            float4 v = *reinterpret_cast<const float4*>(w_fuse + (size_t)(o0 + row) * 1024 + k0 + kq);
            unsigned* dst = &As[row * AS_STRIDE + kq];
            dst[0] = f2tf32(v.x); dst[1] = f2tf32(v.y); dst[2] = f2tf32(v.z); dst[3] = f2tf32(v.w);
        }
        // X tile: X[k0..k0+31][p0..p0+127]
        #pragma unroll
        for (int ps = 0; ps < 4; ++ps) {
            const int row = (tid >> 5) + ps * 8;
            const int cq  = (tid & 31) * 4;
            float4 v = *reinterpret_cast<const float4*>(xb + (size_t)(krow + row) * HW + p0 + cq);
            unsigned* dst = &Xs[row * XS_STRIDE + cq];
            dst[0] = f2tf32(v.x); dst[1] = f2tf32(v.y); dst[2] = f2tf32(v.z); dst[3] = f2tf32(v.w);
        }
        __syncthreads();
        #pragma unroll
        for (int kk = 0; kk < 4; ++kk) {
            unsigned afr[4][4], bfr[4][2];
            const int ka = kk * 8 + (lane & 3);
            const int ra = wm * 64 + (lane >> 2);
            #pragma unroll
            for (int mi = 0; mi < 4; ++mi) {
                const unsigned* ap = &As[(ra + mi * 16) * AS_STRIDE + ka];
                afr[mi][0] = ap[0];
                afr[mi][1] = ap[8 * AS_STRIDE];
                afr[mi][2] = ap[4];
                afr[mi][3] = ap[8 * AS_STRIDE + 4];
            }
            const int cb = wn * 32 + (lane >> 2);
            #pragma unroll
            for (int ni = 0; ni < 4; ++ni) {
                const unsigned* bp = &Xs[ka * XS_STRIDE + cb + ni * 8];
                bfr[ni][0] = bp[0];
                bfr[ni][1] = bp[4 * XS_STRIDE];
            }
            #pragma unroll
            for (int mi = 0; mi < 4; ++mi)
                #pragma unroll
                for (int ni = 0; ni < 4; ++ni)
                    mma_tf32(acc[mi][ni], afr[mi], bfr[ni]);
        }
    }

    // Epilogue: multiply by (sh1*sw1 + sh2*sw2), write float2 pairs.
    const float* sh1 = g_s + (((size_t)0 * BB + b) * CHN) * 80;
    const float* sw1 = g_s + (((size_t)1 * BB + b) * CHN) * 80;
    const float* sh2 = g_s + (((size_t)2 * BB + b) * CHN) * 80;
    const float* sw2 = g_s + (((size_t)3 * BB + b) * CHN) * 80;
    float* outB = out + (size_t)b * CHN * HW;

    #pragma unroll
    for (int mi = 0; mi < 4; ++mi) {
        const int r = o0 + wm * 64 + mi * 16 + (lane >> 2);
        #pragma unroll
        for (int ni = 0; ni < 4; ++ni) {
            const int pc = p0 + wn * 32 + ni * 8 + 2 * (lane & 3);  // even col
            const int h = pc / 80;
            const int w = pc - h * 80;        // w even, w+1 stays in same row
            // rows r and r+8
            #pragma unroll
            for (int half = 0; half < 2; ++half) {
                const int o = r + half * 8;
                const float sh1v = sh1[o * 80 + h];
                const float sh2v = sh2[o * 80 + h];
                const float g0 = sh1v * sw1[o * 80 + w]     + sh2v * sw2[o * 80 + w];
                const float g1 = sh1v * sw1[o * 80 + w + 1] + sh2v * sw2[o * 80 + w + 1];
                float2 v;
                v.x = acc[mi][ni][half * 2 + 0] * g0;
                v.y = acc[mi][ni][half * 2 + 1] * g1;
                *reinterpret_cast<float2*>(outB + (size_t)o * HW + pc) = v;
            }
        }
    }
}

// ---------------- launch ----------------
extern "C" void kernel_launch(void* const* d_in, const int* in_sizes, int n_in,
                              void* d_out, int out_size) {
    const float* rgb    = (const float*)d_in[0];
    const float* t      = (const float*)d_in[1];
    const float* w_fuse = (const float*)d_in[2];
    const float* w_r1   = (const float*)d_in[3];
    const float* w_t1   = (const float*)d_in[4];
    const float* w_fh1  = (const float*)d_in[5];
    const float* w_fw1  = (const float*)d_in[6];
    const float* w_fh2  = (const float*)d_in[7];
    const float* w_fw2  = (const float*)d_in[8];
    const float* bn_g   = (const float*)d_in[9];
    const float* bn_b   = (const float*)d_in[10];
    const float* bn_m   = (const float*)d_in[11];
    const float* bn_v   = (const float*)d_in[12];
    float* out = (float*)d_out;

    mean_kernel<<<dim3(CHN, BB, 2), 256>>>(rgb, t);
    yz_kernel<<<dim3(160, BB, 2), 256>>>(w_r1, w_t1, bn_g, bn_b, bn_m, bn_v);
    s_kernel<<<dim3(4, BB), 256>>>(w_fh1, w_fw1, w_fh2, w_fw2);
    gemm_kernel<<<dim3(HW / BN, CHN / BM, BB), 256>>>(rgb, t, w_fuse, out);
}

// round 3
// speedup vs baseline: 1.1780x; 1.1780x over previous
#include <cuda_runtime.h>
#include <cuda_bf16.h>
#include <cstdint>

// Problem constants
#define BB 8
#define CHN 512
#define HH 80
#define WW 80
#define HW 6400
#define CR 32

// ---------------- device scratch ----------------
// g_means layout: [z][b][p][c]  (p: 0..79 h-means, 80..159 w-means; c: 0..511)
__device__ float g_means[2 * BB * 160 * CHN];
__device__ float g_yz[2 * BB * CR * 160];       // [z][b][cr][160]
__device__ float g_s[4 * BB * CHN * 80];        // [a][b][o][80] : a = {sh1, sw1, sh2, sw2}

// ---------------- helpers ----------------
__device__ __forceinline__ unsigned f2tf32(float x) {
    unsigned u;
    asm("cvt.rna.tf32.f32 %0, %1;" : "=r"(u) : "f"(x));
    return u;
}

__device__ __forceinline__ void mma_tf32(float d[4], const unsigned a[4], const unsigned b[2]) {
    asm volatile(
        "mma.sync.aligned.m16n8k8.row.col.f32.tf32.tf32.f32 "
        "{%0,%1,%2,%3}, {%4,%5,%6,%7}, {%8,%9}, {%0,%1,%2,%3};\n"
        : "+f"(d[0]), "+f"(d[1]), "+f"(d[2]), "+f"(d[3])
        : "r"(a[0]), "r"(a[1]), "r"(a[2]), "r"(a[3]), "r"(b[0]), "r"(b[1]));
}

#define CP_ASYNC16(dst_u32, src_ptr) \
    asm volatile("cp.async.cg.shared.global [%0], [%1], 16;\n" :: "r"(dst_u32), "l"(src_ptr))
#define CP_COMMIT() asm volatile("cp.async.commit_group;\n" ::)
#define CP_WAIT1()  asm volatile("cp.async.wait_group 1;\n" ::)

// ---------------- kernel A: H-means and W-means of rgb and t ----------------
__global__ void mean_kernel(const float* __restrict__ rgb, const float* __restrict__ t) {
    const int c = blockIdx.x;
    const int b = blockIdx.y;
    const int z = blockIdx.z;
    const float* src = (z ? t : rgb) + ((size_t)(b * CHN) + c) * HW;
    __shared__ float sm[HW];
    const int tid = threadIdx.x;
    const float4* src4 = reinterpret_cast<const float4*>(src);
    float4* sm4 = reinterpret_cast<float4*>(sm);
    for (int i = tid; i < HW / 4; i += 256) sm4[i] = src4[i];
    __syncthreads();
    // output: [z][b][p][c]
    float* dst = g_means + (((size_t)z * BB + b) * 160) * CHN + c;
    if (tid < 80) {
        float s = 0.f;
        const float4* r4 = reinterpret_cast<const float4*>(sm + tid * 80);
        #pragma unroll
        for (int w = 0; w < 20; ++w) { float4 v = r4[w]; s += v.x + v.y + v.z + v.w; }
        dst[(size_t)tid * CHN] = s * (1.f / 80.f);
    } else if (tid < 160) {
        const int w = tid - 80;
        float s = 0.f;
        #pragma unroll 8
        for (int h = 0; h < 80; ++h) s += sm[h * 80 + w];
        dst[(size_t)tid * CHN] = s * (1.f / 80.f);
    }
}

// ---------------- kernel B1: tiny GEMM  y/z[cr, p] = W[cr, :] . means[p, :] ----------------
// grid (20, BB, 2), 256 threads. Each block: 8 positions x 32 cr outputs.
__global__ void yz_kernel(const float* __restrict__ w_r1, const float* __restrict__ w_t1,
                          const float* __restrict__ bn_g, const float* __restrict__ bn_b,
                          const float* __restrict__ bn_m, const float* __restrict__ bn_v) {
    const int p0 = blockIdx.x * 8;
    const int b  = blockIdx.y;
    const int z  = blockIdx.z;
    const float* wsrc = z ? w_t1 : w_r1;   // (32, 512) row-major
    const float* xbase = g_means + (((size_t)z * BB + b) * 160 + p0) * CHN;

    __shared__ float w_s[256 * 33];   // [cc][cr] padded
    __shared__ float x_s[8 * 256];    // [p_local][cc]

    const int tid = threadIdx.x;
    const int cr = tid & 31;
    const int pl = tid >> 5;
    float acc = 0.f;

    for (int half = 0; half < 2; ++half) {
        if (half) __syncthreads();
        const int c0 = half * 256;
        // load W chunk transposed: w_s[cc][crr] = w[crr][c0+cc]
        for (int j = tid; j < 32 * 256; j += 256) {
            const int cc = j & 255, crr = j >> 8;
            w_s[cc * 33 + crr] = wsrc[crr * CHN + c0 + cc];
        }
        // load x chunk: x_s[pl][cc] = means[p0+pl][c0+cc]
        for (int j = tid; j < 8 * 256; j += 256) {
            const int ppl = j >> 8, cc = j & 255;
            x_s[ppl * 256 + cc] = xbase[(size_t)ppl * CHN + c0 + cc];
        }
        __syncthreads();
        #pragma unroll 8
        for (int cc = 0; cc < 256; ++cc)
            acc += w_s[cc * 33 + cr] * x_s[pl * 256 + cc];
    }

    float s = acc;
    if (z == 0) {
        const float sc = bn_g[cr] * rsqrtf(bn_v[cr] + 1e-5f);
        s = s * sc + (bn_b[cr] - bn_m[cr] * sc);
    }
    s = fmaxf(s, 0.f);
    g_yz[(((size_t)z * BB + b) * CR + cr) * 160 + p0 + pl] = s;
}

// ---------------- kernel B2: sigmoid gates s_h1, s_w1, s_h2, s_w2 ----------------
__global__ void s_kernel(const float* __restrict__ w_fh1, const float* __restrict__ w_fw1,
                         const float* __restrict__ w_fh2, const float* __restrict__ w_fw2) {
    const int a = blockIdx.x;    // 0..3
    const int b = blockIdx.y;    // 0..7
    const float* wp = (a == 0) ? w_fh1 : (a == 1) ? w_fw1 : (a == 2) ? w_fh2 : w_fw2;  // (512, 32)
    const int z = a >> 1;
    const int off = (a & 1) * 80;
    __shared__ float ys[CR][80];
    const int tid = threadIdx.x;
    for (int i = tid; i < CR * 80; i += 256) {
        const int cr = i / 80, p = i % 80;
        ys[cr][p] = g_yz[(((size_t)z * BB + b) * CR + cr) * 160 + off + p];
    }
    __syncthreads();
    for (int idx = tid; idx < CHN * 80; idx += 256) {
        const int o = idx / 80, h = idx % 80;
        float s = 0.f;
        #pragma unroll
        for (int cr = 0; cr < CR; ++cr) s += wp[o * CR + cr] * ys[cr][h];
        s = 1.f / (1.f + __expf(-s));
        g_s[(((size_t)a * BB + b) * CHN + o) * 80 + h] = s;
    }
}

// ---------------- kernel C: main tf32 GEMM + gated epilogue, 3-stage cp.async ----------------
#define BM 128
#define BN 128
#define BK 32
#define AS_STRIDE 36
#define XS_STRIDE 136
#define STAGE_FLOATS (BM * AS_STRIDE + BK * XS_STRIDE)   // 4608 + 4352 = 8960
#define NSTAGE 3
#define GEMM_SMEM (NSTAGE * STAGE_FLOATS * 4)            // 107520 bytes

__global__ __launch_bounds__(256, 2)
void gemm_kernel(const float* __restrict__ rgb, const float* __restrict__ t,
                 const float* __restrict__ w_fuse, float* __restrict__ out) {
    extern __shared__ float dynsmem[];

    const int b  = blockIdx.z;
    const int o0 = blockIdx.y * BM;
    const int p0 = blockIdx.x * BN;
    const int tid  = threadIdx.x;
    const int lane = tid & 31;
    const int warp = tid >> 5;
    const int wm = warp >> 2;      // 0..1
    const int wn = warp & 3;       // 0..3

    const float* rgbB = rgb + (size_t)b * CHN * HW;
    const float* tB   = t   + (size_t)b * CHN * HW;

    float acc[4][4][4];
    #pragma unroll
    for (int i = 0; i < 4; ++i)
        #pragma unroll
        for (int j = 0; j < 4; ++j)
            #pragma unroll
            for (int e = 0; e < 4; ++e) acc[i][j][e] = 0.f;

    // async load of one k-tile into a stage
    auto issue = [&](int stage, int kt) {
        const int k0 = kt * BK;
        const float* xb = (k0 < CHN) ? rgbB : tB;
        const int krow = k0 & (CHN - 1);
        float* As = dynsmem + stage * STAGE_FLOATS;
        float* Xs = As + BM * AS_STRIDE;
        #pragma unroll
        for (int ps = 0; ps < 4; ++ps) {
            const int row = (tid >> 3) + ps * 32;
            const int kq  = (tid & 7) * 4;
            unsigned d = (unsigned)__cvta_generic_to_shared(&As[row * AS_STRIDE + kq]);
            CP_ASYNC16(d, w_fuse + (size_t)(o0 + row) * 1024 + k0 + kq);
        }
        #pragma unroll
        for (int ps = 0; ps < 4; ++ps) {
            const int row = (tid >> 5) + ps * 8;
            const int cq  = (tid & 31) * 4;
            unsigned d = (unsigned)__cvta_generic_to_shared(&Xs[row * XS_STRIDE + cq]);
            CP_ASYNC16(d, xb + (size_t)(krow + row) * HW + p0 + cq);
        }
    };

    issue(0, 0); CP_COMMIT();
    issue(1, 1); CP_COMMIT();

    for (int kt = 0; kt < 1024 / BK; ++kt) {
        CP_WAIT1();
        __syncthreads();
        if (kt + 2 < 1024 / BK) issue((kt + 2) % NSTAGE, kt + 2);
        CP_COMMIT();

        const float* As = dynsmem + (kt % NSTAGE) * STAGE_FLOATS;
        const float* Xs = As + BM * AS_STRIDE;

        #pragma unroll
        for (int kk = 0; kk < 4; ++kk) {
            unsigned afr[4][4], bfr[4][2];
            const int ka = kk * 8 + (lane & 3);
            const int ra = wm * 64 + (lane >> 2);
            #pragma unroll
            for (int mi = 0; mi < 4; ++mi) {
                const float* ap = &As[(ra + mi * 16) * AS_STRIDE + ka];
                afr[mi][0] = f2tf32(ap[0]);
                afr[mi][1] = f2tf32(ap[8 * AS_STRIDE]);
                afr[mi][2] = f2tf32(ap[4]);
                afr[mi][3] = f2tf32(ap[8 * AS_STRIDE + 4]);
            }
            const int cb = wn * 32 + (lane >> 2);
            #pragma unroll
            for (int ni = 0; ni < 4; ++ni) {
                const float* bp = &Xs[ka * XS_STRIDE + cb + ni * 8];
                bfr[ni][0] = f2tf32(bp[0]);
                bfr[ni][1] = f2tf32(bp[4 * XS_STRIDE]);
            }
            #pragma unroll
            for (int mi = 0; mi < 4; ++mi)
                #pragma unroll
                for (int ni = 0; ni < 4; ++ni)
                    mma_tf32(acc[mi][ni], afr[mi], bfr[ni]);
        }
    }

    // Epilogue: multiply by (sh1*sw1 + sh2*sw2), write float2 pairs.
    const float* sh1 = g_s + (((size_t)0 * BB + b) * CHN) * 80;
    const float* sw1 = g_s + (((size_t)1 * BB + b) * CHN) * 80;
    const float* sh2 = g_s + (((size_t)2 * BB + b) * CHN) * 80;
    const float* sw2 = g_s + (((size_t)3 * BB + b) * CHN) * 80;
    float* outB = out + (size_t)b * CHN * HW;

    #pragma unroll
    for (int mi = 0; mi < 4; ++mi) {
        const int r = o0 + wm * 64 + mi * 16 + (lane >> 2);
        #pragma unroll
        for (int ni = 0; ni < 4; ++ni) {
            const int pc = p0 + wn * 32 + ni * 8 + 2 * (lane & 3);
            const int h = pc / 80;
            const int w = pc - h * 80;
            #pragma unroll
            for (int half = 0; half < 2; ++half) {
                const int o = r + half * 8;
                const float sh1v = sh1[o * 80 + h];
                const float sh2v = sh2[o * 80 + h];
                const float g0 = sh1v * sw1[o * 80 + w]     + sh2v * sw2[o * 80 + w];
                const float g1 = sh1v * sw1[o * 80 + w + 1] + sh2v * sw2[o * 80 + w + 1];
                float2 v;
                v.x = acc[mi][ni][half * 2 + 0] * g0;
                v.y = acc[mi][ni][half * 2 + 1] * g1;
                *reinterpret_cast<float2*>(outB + (size_t)o * HW + pc) = v;
            }
        }
    }
}

// ---------------- launch ----------------
extern "C" void kernel_launch(void* const* d_in, const int* in_sizes, int n_in,
                              void* d_out, int out_size) {
    const float* rgb    = (const float*)d_in[0];
    const float* t      = (const float*)d_in[1];
    const float* w_fuse = (const float*)d_in[2];
    const float* w_r1   = (const float*)d_in[3];
    const float* w_t1   = (const float*)d_in[4];
    const float* w_fh1  = (const float*)d_in[5];
    const float* w_fw1  = (const float*)d_in[6];
    const float* w_fh2  = (const float*)d_in[7];
    const float* w_fw2  = (const float*)d_in[8];
    const float* bn_g   = (const float*)d_in[9];
    const float* bn_b   = (const float*)d_in[10];
    const float* bn_m   = (const float*)d_in[11];
    const float* bn_v   = (const float*)d_in[12];
    float* out = (float*)d_out;

    cudaFuncSetAttribute(gemm_kernel, cudaFuncAttributeMaxDynamicSharedMemorySize, GEMM_SMEM);

    mean_kernel<<<dim3(CHN, BB, 2), 256>>>(rgb, t);
    yz_kernel<<<dim3(20, BB, 2), 256>>>(w_r1, w_t1, bn_g, bn_b, bn_m, bn_v);
    s_kernel<<<dim3(4, BB), 256>>>(w_fh1, w_fw1, w_fh2, w_fw2);
    gemm_kernel<<<dim3(HW / BN, CHN / BM, BB), 256, GEMM_SMEM>>>(rgb, t, w_fuse, out);
}

// round 6
// speedup vs baseline: 1.2835x; 1.0896x over previous
#include <cuda_runtime.h>
#include <cuda_bf16.h>
#include <cstdint>

// Problem constants
#define BB 8
#define CHN 512
#define HH 80
#define WW 80
#define HW 6400
#define CR 32

// ---------------- device scratch ----------------
__device__ float g_means[2 * BB * 160 * CHN];   // [z][b][p][c]
__device__ float g_yz[2 * BB * CR * 160];       // [z][b][cr][160]
__device__ float g_s[4 * BB * CHN * 80];        // [a][b][o][80]
// W repacked to fragment-order tf32: [o_blk][kt][kk][wm][mi][lane][4]
__device__ float g_wr[CHN * 1024];

// ---------------- helpers ----------------
__device__ __forceinline__ unsigned f2tf32(float x) {
    unsigned u;
    asm("cvt.rna.tf32.f32 %0, %1;" : "=r"(u) : "f"(x));
    return u;
}

__device__ __forceinline__ void mma_tf32(float d[4], const unsigned a0, const unsigned a1,
                                         const unsigned a2, const unsigned a3,
                                         const unsigned b0, const unsigned b1) {
    asm volatile(
        "mma.sync.aligned.m16n8k8.row.col.f32.tf32.tf32.f32 "
        "{%0,%1,%2,%3}, {%4,%5,%6,%7}, {%8,%9}, {%0,%1,%2,%3};\n"
        : "+f"(d[0]), "+f"(d[1]), "+f"(d[2]), "+f"(d[3])
        : "r"(a0), "r"(a1), "r"(a2), "r"(a3), "r"(b0), "r"(b1));
}

#define CP_ASYNC16(dst_u32, src_ptr) \
    asm volatile("cp.async.cg.shared.global [%0], [%1], 16;\n" :: "r"(dst_u32), "l"(src_ptr))
#define CP_COMMIT() asm volatile("cp.async.commit_group;\n" ::)
#define CP_WAIT1()  asm volatile("cp.async.wait_group 1;\n" ::)

// ---------------- kernel W-repack: fragment-order tf32 ----------------
// granule id gid in 0..1023 per (o_blk, kt):
//   lane = gid&31, mi = (gid>>5)&3, wm = (gid>>7)&1, kk = (gid>>8)&3
//   R  = o_blk*128 + wm*64 + mi*16 + (lane>>2)
//   Ka = kt*32 + kk*8 + (lane&3)
//   granule = { W[R][Ka], W[R+8][Ka], W[R][Ka+4], W[R+8][Ka+4] }  (RNA tf32)
__global__ void wrepack_kernel(const float* __restrict__ w) {
    const int blk = blockIdx.x;          // o_blk*32 + kt
    const int o_blk = blk >> 5, kt = blk & 31;
    const int tid = threadIdx.x;
    #pragma unroll
    for (int i = 0; i < 4; ++i) {
        const int gid = tid + i * 256;
        const int lane = gid & 31;
        const int mi = (gid >> 5) & 3;
        const int wm = (gid >> 7) & 1;
        const int kk = (gid >> 8) & 3;
        const int R  = o_blk * 128 + wm * 64 + mi * 16 + (lane >> 2);
        const int Ka = kt * 32 + kk * 8 + (lane & 3);
        uint4 o;
        o.x = f2tf32(w[(size_t)R * 1024 + Ka]);
        o.y = f2tf32(w[(size_t)(R + 8) * 1024 + Ka]);
        o.z = f2tf32(w[(size_t)R * 1024 + Ka + 4]);
        o.w = f2tf32(w[(size_t)(R + 8) * 1024 + Ka + 4]);
        reinterpret_cast<uint4*>(g_wr)[(size_t)blk * 1024 + gid] = o;
    }
}

// ---------------- kernel A: H-means and W-means of rgb and t ----------------
__global__ void mean_kernel(const float* __restrict__ rgb, const float* __restrict__ t) {
    const int c = blockIdx.x;
    const int b = blockIdx.y;
    const int z = blockIdx.z;
    const float* src = (z ? t : rgb) + ((size_t)(b * CHN) + c) * HW;
    __shared__ float sm[HW];
    const int tid = threadIdx.x;
    const float4* src4 = reinterpret_cast<const float4*>(src);
    float4* sm4 = reinterpret_cast<float4*>(sm);
    for (int i = tid; i < HW / 4; i += 256) sm4[i] = src4[i];
    __syncthreads();
    float* dst = g_means + (((size_t)z * BB + b) * 160) * CHN + c;
    if (tid < 80) {
        float s = 0.f;
        const float4* r4 = reinterpret_cast<const float4*>(sm + tid * 80);
        #pragma unroll
        for (int w = 0; w < 20; ++w) { float4 v = r4[w]; s += v.x + v.y + v.z + v.w; }
        dst[(size_t)tid * CHN] = s * (1.f / 80.f);
    } else if (tid < 160) {
        const int w = tid - 80;
        float s = 0.f;
        #pragma unroll 8
        for (int h = 0; h < 80; ++h) s += sm[h * 80 + w];
        dst[(size_t)(tid) * CHN] = s * (1.f / 80.f);
    }
}

// ---------------- kernel B1: tiny GEMM + BN/relu ----------------
__global__ void yz_kernel(const float* __restrict__ w_r1, const float* __restrict__ w_t1,
                          const float* __restrict__ bn_g, const float* __restrict__ bn_b,
                          const float* __restrict__ bn_m, const float* __restrict__ bn_v) {
    const int p0 = blockIdx.x * 8;
    const int b  = blockIdx.y;
    const int z  = blockIdx.z;
    const float* wsrc = z ? w_t1 : w_r1;
    const float* xbase = g_means + (((size_t)z * BB + b) * 160 + p0) * CHN;

    __shared__ float w_s[256 * 33];
    __shared__ float x_s[8 * 256];

    const int tid = threadIdx.x;
    const int cr = tid & 31;
    const int pl = tid >> 5;
    float acc = 0.f;

    for (int half = 0; half < 2; ++half) {
        if (half) __syncthreads();
        const int c0 = half * 256;
        for (int j = tid; j < 32 * 256; j += 256) {
            const int cc = j & 255, crr = j >> 8;
            w_s[cc * 33 + crr] = wsrc[crr * CHN + c0 + cc];
        }
        for (int j = tid; j < 8 * 256; j += 256) {
            const int ppl = j >> 8, cc = j & 255;
            x_s[ppl * 256 + cc] = xbase[(size_t)ppl * CHN + c0 + cc];
        }
        __syncthreads();
        #pragma unroll 8
        for (int cc = 0; cc < 256; ++cc)
            acc += w_s[cc * 33 + cr] * x_s[pl * 256 + cc];
    }

    float s = acc;
    if (z == 0) {
        const float sc = bn_g[cr] * rsqrtf(bn_v[cr] + 1e-5f);
        s = s * sc + (bn_b[cr] - bn_m[cr] * sc);
    }
    s = fmaxf(s, 0.f);
    g_yz[(((size_t)z * BB + b) * CR + cr) * 160 + p0 + pl] = s;
}

// ---------------- kernel B2: sigmoid gates ----------------
__global__ void s_kernel(const float* __restrict__ w_fh1, const float* __restrict__ w_fw1,
                         const float* __restrict__ w_fh2, const float* __restrict__ w_fw2) {
    const int a = blockIdx.x;
    const int b = blockIdx.y;
    const float* wp = (a == 0) ? w_fh1 : (a == 1) ? w_fw1 : (a == 2) ? w_fh2 : w_fw2;
    const int z = a >> 1;
    const int off = (a & 1) * 80;
    __shared__ float ys[CR][80];
    const int tid = threadIdx.x;
    for (int i = tid; i < CR * 80; i += 256) {
        const int cr = i / 80, p = i % 80;
        ys[cr][p] = g_yz[(((size_t)z * BB + b) * CR + cr) * 160 + off + p];
    }
    __syncthreads();
    for (int idx = tid; idx < CHN * 80; idx += 256) {
        const int o = idx / 80, h = idx % 80;
        float s = 0.f;
        #pragma unroll
        for (int cr = 0; cr < CR; ++cr) s += wp[o * CR + cr] * ys[cr][h];
        s = 1.f / (1.f + __expf(-s));
        g_s[(((size_t)a * BB + b) * CHN + o) * 80 + h] = s;
    }
}

// ---------------- kernel C: tf32 mma.sync GEMM, fragment-order A, 3-stage cp.async ----------------
#define BM 128
#define BN 128
#define BK 32
#define A_STAGE_FLOATS 4096               // 128x32 in fragment order, no padding needed
#define XS_STRIDE 136
#define X_STAGE_FLOATS (BK * XS_STRIDE)   // 4352
#define STAGE_FLOATS (A_STAGE_FLOATS + X_STAGE_FLOATS)  // 8448
#define NSTAGE 3
#define GEMM_SMEM (NSTAGE * STAGE_FLOATS * 4)           // 101376 bytes

__global__ __launch_bounds__(256, 2)
void gemm_kernel(const float* __restrict__ rgb, const float* __restrict__ t,
                 float* __restrict__ out) {
    extern __shared__ float dynsmem[];

    const int b  = blockIdx.z;
    const int o_blk = blockIdx.y;
    const int o0 = o_blk * BM;
    const int p0 = blockIdx.x * BN;
    const int tid  = threadIdx.x;
    const int lane = tid & 31;
    const int warp = tid >> 5;
    const int wm = warp >> 2;      // 0..1
    const int wn = warp & 3;       // 0..3

    const float* rgbB = rgb + (size_t)b * CHN * HW;
    const float* tB   = t   + (size_t)b * CHN * HW;
    const float* wbase = g_wr + (size_t)o_blk * 32 * A_STAGE_FLOATS;

    float acc[4][4][4];
    #pragma unroll
    for (int i = 0; i < 4; ++i)
        #pragma unroll
        for (int j = 0; j < 4; ++j)
            #pragma unroll
            for (int e = 0; e < 4; ++e) acc[i][j][e] = 0.f;

    auto issue = [&](int stage, int kt) {
        const int k0 = kt * BK;
        const float* xb = (k0 < CHN) ? rgbB : tB;
        const int krow = k0 & (CHN - 1);
        float* As = dynsmem + stage * STAGE_FLOATS;
        float* Xs = As + A_STAGE_FLOATS;
        // A: linear copy of the pre-packed 16KB fragment image
        const float* asrc = wbase + (size_t)kt * A_STAGE_FLOATS;
        #pragma unroll
        for (int ps = 0; ps < 4; ++ps) {
            const int off = (tid + ps * 256) * 4;
            unsigned d = (unsigned)__cvta_generic_to_shared(&As[off]);
            CP_ASYNC16(d, asrc + off);
        }
        // X tile: X[k0..k0+31][p0..p0+127]
        #pragma unroll
        for (int ps = 0; ps < 4; ++ps) {
            const int row = (tid >> 5) + ps * 8;
            const int cq  = (tid & 31) * 4;
            unsigned d = (unsigned)__cvta_generic_to_shared(&Xs[row * XS_STRIDE + cq]);
            CP_ASYNC16(d, xb + (size_t)(krow + row) * HW + p0 + cq);
        }
    };

    issue(0, 0); CP_COMMIT();
    issue(1, 1); CP_COMMIT();

    for (int kt = 0; kt < 1024 / BK; ++kt) {
        CP_WAIT1();
        __syncthreads();
        if (kt + 2 < 1024 / BK) issue((kt + 2) % NSTAGE, kt + 2);
        CP_COMMIT();

        const float* As = dynsmem + (kt % NSTAGE) * STAGE_FLOATS;
        const float* Xs = As + A_STAGE_FLOATS;
        const uint4* a4 = reinterpret_cast<const uint4*>(As);

        #pragma unroll
        for (int kk = 0; kk < 4; ++kk) {
            // A fragments: one LDS.128 each, already tf32
            uint4 av[4];
            #pragma unroll
            for (int mi = 0; mi < 4; ++mi)
                av[mi] = a4[((kk * 2 + wm) * 4 + mi) * 32 + lane];
            // B fragments
            unsigned bfr[4][2];
            const int ka = kk * 8 + (lane & 3);
            const int cb = wn * 32 + (lane >> 2);
            #pragma unroll
            for (int ni = 0; ni < 4; ++ni) {
                const float* bp = &Xs[ka * XS_STRIDE + cb + ni * 8];
                bfr[ni][0] = f2tf32(bp[0]);
                bfr[ni][1] = f2tf32(bp[4 * XS_STRIDE]);
            }
            #pragma unroll
            for (int mi = 0; mi < 4; ++mi)
                #pragma unroll
                for (int ni = 0; ni < 4; ++ni)
                    mma_tf32(acc[mi][ni], av[mi].x, av[mi].y, av[mi].z, av[mi].w,
                             bfr[ni][0], bfr[ni][1]);
        }
    }

    // Epilogue: multiply by (sh1*sw1 + sh2*sw2), write float2 pairs.
    const float* sh1 = g_s + (((size_t)0 * BB + b) * CHN) * 80;
    const float* sw1 = g_s + (((size_t)1 * BB + b) * CHN) * 80;
    const float* sh2 = g_s + (((size_t)2 * BB + b) * CHN) * 80;
    const float* sw2 = g_s + (((size_t)3 * BB + b) * CHN) * 80;
    float* outB = out + (size_t)b * CHN * HW;

    #pragma unroll
    for (int mi = 0; mi < 4; ++mi) {
        const int r = o0 + wm * 64 + mi * 16 + (lane >> 2);
        #pragma unroll
        for (int ni = 0; ni < 4; ++ni) {
            const int pc = p0 + wn * 32 + ni * 8 + 2 * (lane & 3);
            const int h = pc / 80;
            const int w = pc - h * 80;
            #pragma unroll
            for (int half = 0; half < 2; ++half) {
                const int o = r + half * 8;
                const float sh1v = sh1[o * 80 + h];
                const float sh2v = sh2[o * 80 + h];
                const float g0 = sh1v * sw1[o * 80 + w]     + sh2v * sw2[o * 80 + w];
                const float g1 = sh1v * sw1[o * 80 + w + 1] + sh2v * sw2[o * 80 + w + 1];
                float2 v;
                v.x = acc[mi][ni][half * 2 + 0] * g0;
                v.y = acc[mi][ni][half * 2 + 1] * g1;
                *reinterpret_cast<float2*>(outB + (size_t)o * HW + pc) = v;
            }
        }
    }
}

// ---------------- launch ----------------
extern "C" void kernel_launch(void* const* d_in, const int* in_sizes, int n_in,
                              void* d_out, int out_size) {
    const float* rgb    = (const float*)d_in[0];
    const float* t      = (const float*)d_in[1];
    const float* w_fuse = (const float*)d_in[2];
    const float* w_r1   = (const float*)d_in[3];
    const float* w_t1   = (const float*)d_in[4];
    const float* w_fh1  = (const float*)d_in[5];
    const float* w_fw1  = (const float*)d_in[6];
    const float* w_fh2  = (const float*)d_in[7];
    const float* w_fw2  = (const float*)d_in[8];
    const float* bn_g   = (const float*)d_in[9];
    const float* bn_b   = (const float*)d_in[10];
    const float* bn_m   = (const float*)d_in[11];
    const float* bn_v   = (const float*)d_in[12];
    float* out = (float*)d_out;

    cudaFuncSetAttribute(gemm_kernel, cudaFuncAttributeMaxDynamicSharedMemorySize, GEMM_SMEM);

    wrepack_kernel<<<128, 256>>>(w_fuse);
    mean_kernel<<<dim3(CHN, BB, 2), 256>>>(rgb, t);
    yz_kernel<<<dim3(20, BB, 2), 256>>>(w_r1, w_t1, bn_g, bn_b, bn_m, bn_v);
    s_kernel<<<dim3(4, BB), 256>>>(w_fh1, w_fw1, w_fh2, w_fw2);
    gemm_kernel<<<dim3(HW / BN, CHN / BM, BB), 256, GEMM_SMEM>>>(rgb, t, out);
}

// round 7
// speedup vs baseline: 1.5354x; 1.1962x over previous
#include <cuda_runtime.h>
#include <cuda_bf16.h>
#include <cstdint>

// Problem constants
#define BB 8
#define CHN 512
#define HH 80
#define WW 80
#define HW 6400
#define CR 32

// ---------------- device scratch ----------------
__device__ float g_means[2 * BB * 160 * CHN];   // [z][b][p][c]
__device__ float g_yz[2 * BB * CR * 160];       // [z][b][cr][160]
__device__ float g_s[4 * BB * CHN * 80];        // [a][b][o][80]
// W repacked to fragment-order tf32: [o_blk][kt][kk][wm][mi][lane][4]
__device__ float g_wr[CHN * 1024];

// ---------------- helpers ----------------
__device__ __forceinline__ unsigned f2tf32(float x) {
    unsigned u;
    asm("cvt.rna.tf32.f32 %0, %1;" : "=r"(u) : "f"(x));
    return u;
}

__device__ __forceinline__ void mma_tf32(float d[4], const unsigned a0, const unsigned a1,
                                         const unsigned a2, const unsigned a3,
                                         const unsigned b0, const unsigned b1) {
    asm volatile(
        "mma.sync.aligned.m16n8k8.row.col.f32.tf32.tf32.f32 "
        "{%0,%1,%2,%3}, {%4,%5,%6,%7}, {%8,%9}, {%0,%1,%2,%3};\n"
        : "+f"(d[0]), "+f"(d[1]), "+f"(d[2]), "+f"(d[3])
        : "r"(a0), "r"(a1), "r"(a2), "r"(a3), "r"(b0), "r"(b1));
}

#define CP_ASYNC16(dst_u32, src_ptr) \
    asm volatile("cp.async.cg.shared.global [%0], [%1], 16;\n" :: "r"(dst_u32), "l"(src_ptr))
#define CP_COMMIT() asm volatile("cp.async.commit_group;\n" ::)
#define CP_WAIT1()  asm volatile("cp.async.wait_group 1;\n" ::)

// ---------------- kernel W-repack: fragment-order tf32 ----------------
__global__ void wrepack_kernel(const float* __restrict__ w) {
    const int blk = blockIdx.x;          // o_blk*32 + kt
    const int o_blk = blk >> 5, kt = blk & 31;
    const int tid = threadIdx.x;
    #pragma unroll
    for (int i = 0; i < 4; ++i) {
        const int gid = tid + i * 256;
        const int lane = gid & 31;
        const int mi = (gid >> 5) & 3;
        const int wm = (gid >> 7) & 1;
        const int kk = (gid >> 8) & 3;
        const int R  = o_blk * 128 + wm * 64 + mi * 16 + (lane >> 2);
        const int Ka = kt * 32 + kk * 8 + (lane & 3);
        uint4 o;
        o.x = f2tf32(w[(size_t)R * 1024 + Ka]);
        o.y = f2tf32(w[(size_t)(R + 8) * 1024 + Ka]);
        o.z = f2tf32(w[(size_t)R * 1024 + Ka + 4]);
        o.w = f2tf32(w[(size_t)(R + 8) * 1024 + Ka + 4]);
        reinterpret_cast<uint4*>(g_wr)[(size_t)blk * 1024 + gid] = o;
    }
}

// ---------------- kernel A: H-means and W-means of rgb and t ----------------
__global__ void mean_kernel(const float* __restrict__ rgb, const float* __restrict__ t) {
    const int c = blockIdx.x;
    const int b = blockIdx.y;
    const int z = blockIdx.z;
    const float* src = (z ? t : rgb) + ((size_t)(b * CHN) + c) * HW;
    __shared__ float sm[HW];
    const int tid = threadIdx.x;
    const float4* src4 = reinterpret_cast<const float4*>(src);
    float4* sm4 = reinterpret_cast<float4*>(sm);
    for (int i = tid; i < HW / 4; i += 256) sm4[i] = src4[i];
    __syncthreads();
    float* dst = g_means + (((size_t)z * BB + b) * 160) * CHN + c;
    if (tid < 80) {
        float s = 0.f;
        const float4* r4 = reinterpret_cast<const float4*>(sm + tid * 80);
        #pragma unroll
        for (int w = 0; w < 20; ++w) { float4 v = r4[w]; s += v.x + v.y + v.z + v.w; }
        dst[(size_t)tid * CHN] = s * (1.f / 80.f);
    } else if (tid < 160) {
        const int w = tid - 80;
        float s = 0.f;
        #pragma unroll 8
        for (int h = 0; h < 80; ++h) s += sm[h * 80 + w];
        dst[(size_t)(tid) * CHN] = s * (1.f / 80.f);
    }
}

// ---------------- kernel B1: tiny GEMM + BN/relu ----------------
__global__ void yz_kernel(const float* __restrict__ w_r1, const float* __restrict__ w_t1,
                          const float* __restrict__ bn_g, const float* __restrict__ bn_b,
                          const float* __restrict__ bn_m, const float* __restrict__ bn_v) {
    const int p0 = blockIdx.x * 8;
    const int b  = blockIdx.y;
    const int z  = blockIdx.z;
    const float* wsrc = z ? w_t1 : w_r1;
    const float* xbase = g_means + (((size_t)z * BB + b) * 160 + p0) * CHN;

    __shared__ float w_s[256 * 33];
    __shared__ float x_s[8 * 256];

    const int tid = threadIdx.x;
    const int cr = tid & 31;
    const int pl = tid >> 5;
    float acc = 0.f;

    for (int half = 0; half < 2; ++half) {
        if (half) __syncthreads();
        const int c0 = half * 256;
        for (int j = tid; j < 32 * 256; j += 256) {
            const int cc = j & 255, crr = j >> 8;
            w_s[cc * 33 + crr] = wsrc[crr * CHN + c0 + cc];
        }
        for (int j = tid; j < 8 * 256; j += 256) {
            const int ppl = j >> 8, cc = j & 255;
            x_s[ppl * 256 + cc] = xbase[(size_t)ppl * CHN + c0 + cc];
        }
        __syncthreads();
        #pragma unroll 8
        for (int cc = 0; cc < 256; ++cc)
            acc += w_s[cc * 33 + cr] * x_s[pl * 256 + cc];
    }

    float s = acc;
    if (z == 0) {
        const float sc = bn_g[cr] * rsqrtf(bn_v[cr] + 1e-5f);
        s = s * sc + (bn_b[cr] - bn_m[cr] * sc);
    }
    s = fmaxf(s, 0.f);
    g_yz[(((size_t)z * BB + b) * CR + cr) * 160 + p0 + pl] = s;
}

// ---------------- kernel B2: sigmoid gates (v2: 256 blocks) ----------------
// grid(4, BB, 8): a, b, o-chunk of 64. Block 256 threads.
__global__ void s_kernel(const float* __restrict__ w_fh1, const float* __restrict__ w_fw1,
                         const float* __restrict__ w_fh2, const float* __restrict__ w_fw2) {
    const int a  = blockIdx.x;
    const int b  = blockIdx.y;
    const int oc = blockIdx.z;              // 0..7, o range [oc*64, oc*64+64)
    const float* wp = (a == 0) ? w_fh1 : (a == 1) ? w_fw1 : (a == 2) ? w_fh2 : w_fw2;  // (512,32)
    const int z = a >> 1;
    const int off = (a & 1) * 80;

    __shared__ float ys[CR][80];            // yz slice
    __shared__ float wch[64][33];           // W chunk, padded

    const int tid = threadIdx.x;
    // load yz slice (32 x 80 = 2560)
    for (int i = tid; i < CR * 80; i += 256) {
        const int cr = i / 80, p = i % 80;
        ys[cr][p] = g_yz[(((size_t)z * BB + b) * CR + cr) * 160 + off + p];
    }
    // load W chunk (64 x 32 = 2048), coalesced
    for (int i = tid; i < 64 * 32; i += 256) {
        const int ol = i >> 5, cr = i & 31;
        wch[ol][cr] = wp[(oc * 64 + ol) * CR + cr];
    }
    __syncthreads();

    const int ol = tid >> 2;          // 0..63
    const int hg = (tid & 3) * 20;    // h base
    float* dst = g_s + (((size_t)a * BB + b) * CHN + oc * 64 + ol) * 80;
    #pragma unroll
    for (int j = 0; j < 20; ++j) {
        const int h = hg + j;
        float s = 0.f;
        #pragma unroll
        for (int cr = 0; cr < CR; ++cr) s += wch[ol][cr] * ys[cr][h];
        dst[h] = 1.f / (1.f + __expf(-s));
    }
}

// ---------------- kernel C: tf32 mma.sync GEMM, fragment-order A, 3-stage cp.async ----------------
#define BM 128
#define BN 128
#define BK 32
#define A_STAGE_FLOATS 4096               // 128x32 in fragment order
#define XS_STRIDE 136
#define X_STAGE_FLOATS (BK * XS_STRIDE)   // 4352
#define STAGE_FLOATS (A_STAGE_FLOATS + X_STAGE_FLOATS)  // 8448
#define NSTAGE 3
#define GEMM_SMEM (NSTAGE * STAGE_FLOATS * 4)           // 101376 bytes

__global__ __launch_bounds__(256, 2)
void gemm_kernel(const float* __restrict__ rgb, const float* __restrict__ t,
                 float* __restrict__ out) {
    extern __shared__ float dynsmem[];

    const int b  = blockIdx.z;
    const int o_blk = blockIdx.y;
    const int o0 = o_blk * BM;
    const int p0 = blockIdx.x * BN;
    const int tid  = threadIdx.x;
    const int lane = tid & 31;
    const int warp = tid >> 5;
    const int wm = warp >> 2;      // 0..1
    const int wn = warp & 3;       // 0..3

    const float* rgbB = rgb + (size_t)b * CHN * HW;
    const float* tB   = t   + (size_t)b * CHN * HW;
    const float* wbase = g_wr + (size_t)o_blk * 32 * A_STAGE_FLOATS;

    float acc[4][4][4];
    #pragma unroll
    for (int i = 0; i < 4; ++i)
        #pragma unroll
        for (int j = 0; j < 4; ++j)
            #pragma unroll
            for (int e = 0; e < 4; ++e) acc[i][j][e] = 0.f;

    auto issue = [&](int stage, int kt) {
        const int k0 = kt * BK;
        const float* xb = (k0 < CHN) ? rgbB : tB;
        const int krow = k0 & (CHN - 1);
        float* As = dynsmem + stage * STAGE_FLOATS;
        float* Xs = As + A_STAGE_FLOATS;
        const float* asrc = wbase + (size_t)kt * A_STAGE_FLOATS;
        #pragma unroll
        for (int ps = 0; ps < 4; ++ps) {
            const int off = (tid + ps * 256) * 4;
            unsigned d = (unsigned)__cvta_generic_to_shared(&As[off]);
            CP_ASYNC16(d, asrc + off);
        }
        #pragma unroll
        for (int ps = 0; ps < 4; ++ps) {
            const int row = (tid >> 5) + ps * 8;
            const int cq  = (tid & 31) * 4;
            unsigned d = (unsigned)__cvta_generic_to_shared(&Xs[row * XS_STRIDE + cq]);
            CP_ASYNC16(d, xb + (size_t)(krow + row) * HW + p0 + cq);
        }
    };

    issue(0, 0); CP_COMMIT();
    issue(1, 1); CP_COMMIT();

    for (int kt = 0; kt < 1024 / BK; ++kt) {
        CP_WAIT1();
        __syncthreads();
        if (kt + 2 < 1024 / BK) issue((kt + 2) % NSTAGE, kt + 2);
        CP_COMMIT();

        const float* As = dynsmem + (kt % NSTAGE) * STAGE_FLOATS;
        const float* Xs = As + A_STAGE_FLOATS;
        const uint4* a4 = reinterpret_cast<const uint4*>(As);

        #pragma unroll
        for (int kk = 0; kk < 4; ++kk) {
            uint4 av[4];
            #pragma unroll
            for (int mi = 0; mi < 4; ++mi)
                av[mi] = a4[((kk * 2 + wm) * 4 + mi) * 32 + lane];
            unsigned bfr[4][2];
            const int ka = kk * 8 + (lane & 3);
            const int cb = wn * 32 + (lane >> 2);
            #pragma unroll
            for (int ni = 0; ni < 4; ++ni) {
                const float* bp = &Xs[ka * XS_STRIDE + cb + ni * 8];
                bfr[ni][0] = f2tf32(bp[0]);
                bfr[ni][1] = f2tf32(bp[4 * XS_STRIDE]);
            }
            #pragma unroll
            for (int mi = 0; mi < 4; ++mi)
                #pragma unroll
                for (int ni = 0; ni < 4; ++ni)
                    mma_tf32(acc[mi][ni], av[mi].x, av[mi].y, av[mi].z, av[mi].w,
                             bfr[ni][0], bfr[ni][1]);
        }
    }

    // Epilogue
    const float* sh1 = g_s + (((size_t)0 * BB + b) * CHN) * 80;
    const float* sw1 = g_s + (((size_t)1 * BB + b) * CHN) * 80;
    const float* sh2 = g_s + (((size_t)2 * BB + b) * CHN) * 80;
    const float* sw2 = g_s + (((size_t)3 * BB + b) * CHN) * 80;
    float* outB = out + (size_t)b * CHN * HW;

    #pragma unroll
    for (int mi = 0; mi < 4; ++mi) {
        const int r = o0 + wm * 64 + mi * 16 + (lane >> 2);
        #pragma unroll
        for (int ni = 0; ni < 4; ++ni) {
            const int pc = p0 + wn * 32 + ni * 8 + 2 * (lane & 3);
            const int h = pc / 80;
            const int w = pc - h * 80;
            #pragma unroll
            for (int half = 0; half < 2; ++half) {
                const int o = r + half * 8;
                const float sh1v = sh1[o * 80 + h];
                const float sh2v = sh2[o * 80 + h];
                const float g0 = sh1v * sw1[o * 80 + w]     + sh2v * sw2[o * 80 + w];
                const float g1 = sh1v * sw1[o * 80 + w + 1] + sh2v * sw2[o * 80 + w + 1];
                float2 v;
                v.x = acc[mi][ni][half * 2 + 0] * g0;
                v.y = acc[mi][ni][half * 2 + 1] * g1;
                *reinterpret_cast<float2*>(outB + (size_t)o * HW + pc) = v;
            }
        }
    }
}

// ---------------- launch ----------------
extern "C" void kernel_launch(void* const* d_in, const int* in_sizes, int n_in,
                              void* d_out, int out_size) {
    const float* rgb    = (const float*)d_in[0];
    const float* t      = (const float*)d_in[1];
    const float* w_fuse = (const float*)d_in[2];
    const float* w_r1   = (const float*)d_in[3];
    const float* w_t1   = (const float*)d_in[4];
    const float* w_fh1  = (const float*)d_in[5];
    const float* w_fw1  = (const float*)d_in[6];
    const float* w_fh2  = (const float*)d_in[7];
    const float* w_fw2  = (const float*)d_in[8];
    const float* bn_g   = (const float*)d_in[9];
    const float* bn_b   = (const float*)d_in[10];
    const float* bn_m   = (const float*)d_in[11];
    const float* bn_v   = (const float*)d_in[12];
    float* out = (float*)d_out;

    cudaFuncSetAttribute(gemm_kernel, cudaFuncAttributeMaxDynamicSharedMemorySize, GEMM_SMEM);

    wrepack_kernel<<<128, 256>>>(w_fuse);
    mean_kernel<<<dim3(CHN, BB, 2), 256>>>(rgb, t);
    yz_kernel<<<dim3(20, BB, 2), 256>>>(w_r1, w_t1, bn_g, bn_b, bn_m, bn_v);
    s_kernel<<<dim3(4, BB, 8), 256>>>(w_fh1, w_fw1, w_fh2, w_fw2);
    gemm_kernel<<<dim3(HW / BN, CHN / BM, BB), 256, GEMM_SMEM>>>(rgb, t, out);
}